// round 1
// baseline (speedup 1.0000x reference)
#include <cuda_runtime.h>

// Problem geometry: (N=2, C=1, D=160, H=192, W=224), win=9, pad=4, zero-padded box sums.
#define NB   2
#define DD   160
#define HH   192
#define WW   224
#define HW   (HH * WW)            // 43008
#define DHW  (DD * HH * WW)       // 6881280
#define VOLI (NB * DHW)           // 13762560
#define PAD  4
#define WINL 9
#define EPSV 1e-5f

#define SZVOL ((size_t)VOLI)

// H-pass chunking: 2 chunks of 96 along H
#define CHUNK_H 96
#define NCH     2
#define T2      (NB * DD * NCH * WW)     // 143360
// D-pass chunking: 2 chunks of 80 along D
#define CHUNK_D 80
#define NCD     2
#define T3      (NB * NCD * HH * WW)     // 172032
#define K3_BLOCKS (T3 / 256)             // 672

// Scratch (allocation-free: static device globals). 5 fields each, ~275 MB per buffer.
__device__ float  g_A[5 * (size_t)VOLI];
__device__ float  g_B[5 * (size_t)VOLI];
__device__ double g_part[K3_BLOCKS];

// ---------------------------------------------------------------------------
// K1: W-axis box sum fused with product formation.
// One block per (n,d,h) row. Shared-memory row with zero halo.
// Writes 5 fields: sumI, sumJ, sumI2, sumJ2, sumIJ.
// ---------------------------------------------------------------------------
__global__ void k1_wpass(const float* __restrict__ I, const float* __restrict__ J) {
    __shared__ float sI[WW + 2 * PAD];
    __shared__ float sJ[WW + 2 * PAD];
    const int t = threadIdx.x;
    const size_t base = (size_t)blockIdx.x * WW;

    if (t < WW + 2 * PAD) {
        int w = t - PAD;
        bool v = (unsigned)w < (unsigned)WW;
        sI[t] = v ? I[base + w] : 0.f;
        sJ[t] = v ? J[base + w] : 0.f;
    }
    __syncthreads();

    if (t < WW) {
        float si = 0.f, sj = 0.f, sii = 0.f, sjj = 0.f, sij = 0.f;
#pragma unroll
        for (int k = 0; k < WINL; k++) {
            float a = sI[t + k];
            float b = sJ[t + k];
            si += a; sj += b;
            sii += a * a; sjj += b * b; sij += a * b;
        }
        size_t idx = base + t;
        g_A[idx]             = si;
        g_A[SZVOL + idx]     = sj;
        g_A[2 * SZVOL + idx] = sii;
        g_A[3 * SZVOL + idx] = sjj;
        g_A[4 * SZVOL + idx] = sij;
    }
}

// ---------------------------------------------------------------------------
// K2: H-axis box sum via per-thread sliding window (add leading / sub trailing).
// Thread = fixed (n, d, w, h-chunk). Coalesced along w.
// ---------------------------------------------------------------------------
__global__ void k2_hpass() {
    int t = blockIdx.x * blockDim.x + threadIdx.x;
    if (t >= T2) return;

    int w = t % WW;
    int r = t / WW;
    int chunk = r & (NCH - 1);
    int plane = r >> 1;                   // n*DD + d
    int h0 = chunk * CHUNK_H;
    size_t base = (size_t)plane * HW + w; // address of (plane, h=0, w)

    float S0 = 0.f, S1 = 0.f, S2 = 0.f, S3 = 0.f, S4 = 0.f;

    // Initial window for output h0: sum over h in [h0-4, h0+4]
#pragma unroll
    for (int k = -PAD; k <= PAD; k++) {
        int hh = h0 + k;
        if ((unsigned)hh < (unsigned)HH) {
            size_t p = base + (size_t)hh * WW;
            S0 += g_A[p];
            S1 += g_A[SZVOL + p];
            S2 += g_A[2 * SZVOL + p];
            S3 += g_A[3 * SZVOL + p];
            S4 += g_A[4 * SZVOL + p];
        }
    }

    for (int h = h0; h < h0 + CHUNK_H; h++) {
        size_t p = base + (size_t)h * WW;
        g_B[p]             = S0;
        g_B[SZVOL + p]     = S1;
        g_B[2 * SZVOL + p] = S2;
        g_B[3 * SZVOL + p] = S3;
        g_B[4 * SZVOL + p] = S4;

        int ha = h + PAD + 1;
        int hs = h - PAD;
        if ((unsigned)ha < (unsigned)HH) {
            size_t q = base + (size_t)ha * WW;
            S0 += g_A[q];
            S1 += g_A[SZVOL + q];
            S2 += g_A[2 * SZVOL + q];
            S3 += g_A[3 * SZVOL + q];
            S4 += g_A[4 * SZVOL + q];
        }
        if ((unsigned)hs < (unsigned)HH) {
            size_t q = base + (size_t)hs * WW;
            S0 -= g_A[q];
            S1 -= g_A[SZVOL + q];
            S2 -= g_A[2 * SZVOL + q];
            S3 -= g_A[3 * SZVOL + q];
            S4 -= g_A[4 * SZVOL + q];
        }
    }
}

// ---------------------------------------------------------------------------
// K3: D-axis box sum (sliding) fused with the NCC pointwise term + reduction.
// Thread = fixed (n, h, w, d-chunk). Per-block partial sums -> g_part.
// ---------------------------------------------------------------------------
__global__ void k3_dpass() {
    int t = blockIdx.x * blockDim.x + threadIdx.x;
    float local = 0.f;

    if (t < T3) {
        int w = t % WW;
        int r = t / WW;
        int h = r % HH; r /= HH;
        int chunk = r & (NCD - 1);
        int n = r >> 1;
        int d0 = chunk * CHUNK_D;
        size_t base = (size_t)n * DHW + (size_t)h * WW + w; // (n, d=0, h, w)

        float S0 = 0.f, S1 = 0.f, S2 = 0.f, S3 = 0.f, S4 = 0.f;
#pragma unroll
        for (int k = -PAD; k <= PAD; k++) {
            int dd = d0 + k;
            if ((unsigned)dd < (unsigned)DD) {
                size_t p = base + (size_t)dd * HW;
                S0 += g_B[p];
                S1 += g_B[SZVOL + p];
                S2 += g_B[2 * SZVOL + p];
                S3 += g_B[3 * SZVOL + p];
                S4 += g_B[4 * SZVOL + p];
            }
        }

        const float ws     = 729.f;       // 9^3
        const float inv_ws = 1.f / 729.f;

        for (int d = d0; d < d0 + CHUNK_D; d++) {
            float ui = S0 * inv_ws;
            float uj = S1 * inv_ws;
            float cross = S4 - uj * S0 - ui * S1 + ui * uj * ws;
            float iv = fmaxf(S2 - 2.f * ui * S0 + ui * ui * ws, EPSV);
            float jv = fmaxf(S3 - 2.f * uj * S1 + uj * uj * ws, EPSV);
            local += (cross * cross) / (iv * jv);

            int da = d + PAD + 1;
            int ds = d - PAD;
            if ((unsigned)da < (unsigned)DD) {
                size_t q = base + (size_t)da * HW;
                S0 += g_B[q];
                S1 += g_B[SZVOL + q];
                S2 += g_B[2 * SZVOL + q];
                S3 += g_B[3 * SZVOL + q];
                S4 += g_B[4 * SZVOL + q];
            }
            if ((unsigned)ds < (unsigned)DD) {
                size_t q = base + (size_t)ds * HW;
                S0 -= g_B[q];
                S1 -= g_B[SZVOL + q];
                S2 -= g_B[2 * SZVOL + q];
                S3 -= g_B[3 * SZVOL + q];
                S4 -= g_B[4 * SZVOL + q];
            }
        }
    }

    // Block reduction (warp shuffle + smem), deterministic per-block partial.
#pragma unroll
    for (int o = 16; o > 0; o >>= 1)
        local += __shfl_down_sync(0xffffffffu, local, o);

    __shared__ float wsum[8];
    if ((threadIdx.x & 31) == 0) wsum[threadIdx.x >> 5] = local;
    __syncthreads();
    if (threadIdx.x == 0) {
        float s = 0.f;
#pragma unroll
        for (int i = 0; i < 8; i++) s += wsum[i];
        g_part[blockIdx.x] = (double)s;
    }
}

// ---------------------------------------------------------------------------
// Final: deterministic serial sum of 672 block partials, write -mean.
// ---------------------------------------------------------------------------
__global__ void k_final(float* __restrict__ out) {
    double s = 0.0;
    for (int i = 0; i < K3_BLOCKS; i++) s += g_part[i];
    out[0] = (float)(-s / (double)VOLI);
}

extern "C" void kernel_launch(void* const* d_in, const int* in_sizes, int n_in,
                              void* d_out, int out_size) {
    const float* I = (const float*)d_in[0];   // y_true
    const float* J = (const float*)d_in[1];   // y_pred

    k1_wpass<<<NB * DD * HH, 256>>>(I, J);
    k2_hpass<<<(T2 + 255) / 256, 256>>>();
    k3_dpass<<<K3_BLOCKS, 256>>>();
    k_final<<<1, 1>>>((float*)d_out);
}

// round 3
// speedup vs baseline: 1.6065x; 1.6065x over previous
#include <cuda_runtime.h>

// Geometry: (N=2, C=1, D=160, H=192, W=224), win=9, pad=4, zero-padded box sums.
#define NB   2
#define DD   160
#define HH   192
#define WW   224
#define HW   (HH * WW)            // 43008
#define DHW  (DD * HW)            // 6881280
#define VOLI (NB * DHW)           // 13762560
#define PAD  4
#define EPSV 1e-5f
#define SZ   ((size_t)VOLI)

#define CH   96                   // h-chunk per block in kA
#define NSTEPS (CH + 2 * PAD)     // 104 sweep steps

#define CHD  80                   // d-chunk per thread in k3
#define NCD  2
#define T3   (NB * NCD * HH * WW) // 172032
#define K3_BLOCKS (T3 / 256)      // 672

// Scratch: W+H box-summed fields. SoA-ish: float4 = (sumI,sumJ,sumI2,sumJ2), float = sumIJ.
__device__ float4 g_B4[SZ];
__device__ float  g_B1[SZ];
__device__ double g_part[K3_BLOCKS];

// ---------------------------------------------------------------------------
// kA: fused W-pass + H-pass.
// Block = (plane, h-chunk). Thread t owns column w=t. Sweep H ingesting one
// row per step: row loaded to smem (double-buffered), W 9-tap sums computed
// from smem, H window maintained as per-thread register ring of 9 rows x 5
// fields. Unroll by 18 (= lcm(9,2)) so ring slot and buffer index are static.
// ---------------------------------------------------------------------------
__global__ __launch_bounds__(256) void kA(const float* __restrict__ I,
                                          const float* __restrict__ J) {
    __shared__ float sI[2][WW + 2 * PAD];
    __shared__ float sJ[2][WW + 2 * PAD];

    const int t = threadIdx.x;
    const int plane = blockIdx.x;              // n*DD + d
    const int h0 = blockIdx.y * CH;
    const float* Ip = I + (size_t)plane * HW;
    const float* Jp = J + (size_t)plane * HW;
    const size_t obase = (size_t)plane * HW;

    float r0[9], r1[9], r2[9], r3[9], r4[9];
#pragma unroll
    for (int k = 0; k < 9; k++) { r0[k] = r1[k] = r2[k] = r3[k] = r4[k] = 0.f; }
    float S0 = 0.f, S1 = 0.f, S2 = 0.f, S3 = 0.f, S4 = 0.f;

    const int wld = t - PAD;                   // column this thread loads (halo)

    for (int hb = 0; hb < 108; hb += 18) {
#pragma unroll
        for (int k = 0; k < 18; k++) {
            const int step = hb + k;
            if (step < NSTEPS) {               // uniform across block
                const int hh = h0 - PAD + step;
                const int buf = k & 1;
                const int slot = ((hb / 9) * 9 + k) % 9; // == step % 9; hb multiple of 9? no ->
                // hb steps by 18 (multiple of 9), so step % 9 == k % 9:
                const int rs = k % 9;
                (void)slot;

                // load row hh (zero outside volume / W-halo)
                if (t < WW + 2 * PAD) {
                    float vi = 0.f, vj = 0.f;
                    if ((unsigned)hh < (unsigned)HH && (unsigned)wld < (unsigned)WW) {
                        size_t p = (size_t)hh * WW + wld;
                        vi = Ip[p];
                        vj = Jp[p];
                    }
                    sI[buf][t] = vi;
                    sJ[buf][t] = vj;
                }
                __syncthreads();

                if (t < WW) {
                    // W 9-tap sums of products for (row hh, col t)
                    float v0 = 0.f, v1 = 0.f, v2 = 0.f, v3 = 0.f, v4 = 0.f;
#pragma unroll
                    for (int q = 0; q < 9; q++) {
                        float a = sI[buf][t + q];
                        float b = sJ[buf][t + q];
                        v0 += a; v1 += b;
                        v2 += a * a; v3 += b * b; v4 += a * b;
                    }
                    // H sliding window via register ring
                    S0 += v0 - r0[rs]; r0[rs] = v0;
                    S1 += v1 - r1[rs]; r1[rs] = v1;
                    S2 += v2 - r2[rs]; r2[rs] = v2;
                    S3 += v3 - r3[rs]; r3[rs] = v3;
                    S4 += v4 - r4[rs]; r4[rs] = v4;

                    const int ho = hh - PAD;
                    if (ho >= h0 && ho < h0 + CH) {
                        size_t idx = obase + (size_t)ho * WW + t;
                        g_B4[idx] = make_float4(S0, S1, S2, S3);
                        g_B1[idx] = S4;
                    }
                }
                __syncthreads();
            }
        }
    }
}

// ---------------------------------------------------------------------------
// k3: D-axis sliding box sum fused with NCC pointwise loss + block reduction.
// Thread = (n, d-chunk, h, w). Coalesced along w; float4 + float loads.
// ---------------------------------------------------------------------------
__global__ __launch_bounds__(256) void k3_dpass() {
    const int t = blockIdx.x * blockDim.x + threadIdx.x;
    float local = 0.f;

    if (t < T3) {
        int w = t % WW;
        int r = t / WW;
        int h = r % HH; r /= HH;
        int chunk = r & (NCD - 1);
        int n = r >> 1;
        int d0 = chunk * CHD;
        size_t base = (size_t)n * DHW + (size_t)h * WW + w;

        float S0 = 0.f, S1 = 0.f, S2 = 0.f, S3 = 0.f, S4 = 0.f;
#pragma unroll
        for (int k = -PAD; k <= PAD; k++) {
            int dd = d0 + k;
            if ((unsigned)dd < (unsigned)DD) {
                size_t p = base + (size_t)dd * HW;
                float4 f = g_B4[p];
                S0 += f.x; S1 += f.y; S2 += f.z; S3 += f.w;
                S4 += g_B1[p];
            }
        }

        const float ws = 729.f, inv_ws = 1.f / 729.f;

        for (int d = d0; d < d0 + CHD; d++) {
            float ui = S0 * inv_ws;
            float uj = S1 * inv_ws;
            float cross = S4 - uj * S0 - ui * S1 + ui * uj * ws;
            float iv = fmaxf(S2 - 2.f * ui * S0 + ui * ui * ws, EPSV);
            float jv = fmaxf(S3 - 2.f * uj * S1 + uj * uj * ws, EPSV);
            local += (cross * cross) / (iv * jv);

            int da = d + PAD + 1;
            int ds = d - PAD;
            if ((unsigned)da < (unsigned)DD) {
                size_t q = base + (size_t)da * HW;
                float4 f = g_B4[q];
                S0 += f.x; S1 += f.y; S2 += f.z; S3 += f.w;
                S4 += g_B1[q];
            }
            if ((unsigned)ds < (unsigned)DD) {
                size_t q = base + (size_t)ds * HW;
                float4 f = g_B4[q];
                S0 -= f.x; S1 -= f.y; S2 -= f.z; S3 -= f.w;
                S4 -= g_B1[q];
            }
        }
    }

#pragma unroll
    for (int o = 16; o > 0; o >>= 1)
        local += __shfl_down_sync(0xffffffffu, local, o);

    __shared__ float wsum[8];
    if ((threadIdx.x & 31) == 0) wsum[threadIdx.x >> 5] = local;
    __syncthreads();
    if (threadIdx.x == 0) {
        float s = 0.f;
#pragma unroll
        for (int i = 0; i < 8; i++) s += wsum[i];
        g_part[blockIdx.x] = (double)s;
    }
}

// ---------------------------------------------------------------------------
// Final: parallel deterministic reduction of 672 partials.
// ---------------------------------------------------------------------------
__global__ __launch_bounds__(256) void k_final(float* __restrict__ out) {
    __shared__ double sd[256];
    const int t = threadIdx.x;
    double s = 0.0;
    for (int i = t; i < K3_BLOCKS; i += 256) s += g_part[i];
    sd[t] = s;
    __syncthreads();
#pragma unroll
    for (int o = 128; o > 0; o >>= 1) {
        if (t < o) sd[t] += sd[t + o];
        __syncthreads();
    }
    if (t == 0) out[0] = (float)(-sd[0] / (double)VOLI);
}

extern "C" void kernel_launch(void* const* d_in, const int* in_sizes, int n_in,
                              void* d_out, int out_size) {
    const float* I = (const float*)d_in[0];   // y_true
    const float* J = (const float*)d_in[1];   // y_pred

    dim3 gridA(NB * DD, HH / CH);             // (320, 2)
    kA<<<gridA, 256>>>(I, J);
    k3_dpass<<<K3_BLOCKS, 256>>>();
    k_final<<<1, 256>>>((float*)d_out);
}

// round 6
// speedup vs baseline: 1.8973x; 1.1811x over previous
#include <cuda_runtime.h>

// Geometry: (N=2, C=1, D=160, H=192, W=224), win=9, pad=4, zero-padded box sums.
#define NB   2
#define DD   160
#define HH   192
#define WW   224
#define HW   (HH * WW)            // 43008
#define DHW  (DD * HW)            // 6881280
#define VOLI (NB * DHW)           // 13762560
#define PAD  4
#define EPSV 1e-5f
#define SZ   ((size_t)VOLI)

#define CH     64                 // h-chunk per block in kA
#define NSTEPS (CH + 2 * PAD)     // 72 = 4 * 18 exactly

#define CHD  80                   // d-chunk per thread in k3
#define NCD  2
#define T3   (NB * NCD * HH * WW) // 172032
#define K3_BLOCKS (T3 / 256)      // 672

// Scratch: W+H box-summed fields. float4 = (sumI,sumJ,sumI2,sumJ2), float = sumIJ.
__device__ float4 g_B4[SZ];
__device__ float  g_B1[SZ];
__device__ double g_part[K3_BLOCKS];

// ---------------------------------------------------------------------------
// kA: fused W-pass + H-pass, software-pipelined.
// Block = (plane, h-chunk of 64). Thread t owns column w=t. Per step: store
// the prefetched row to smem (double buffered), issue LDG for the next row,
// one __syncthreads, then compute 9-tap W sums + H register-ring slide.
// Unroll 18 (= lcm(ring 9, buffer 2)) keeps ring slot & buffer index static.
// ---------------------------------------------------------------------------
__global__ __launch_bounds__(256) void kA(const float* __restrict__ I,
                                          const float* __restrict__ J) {
    __shared__ float sI[2][WW + 2 * PAD];
    __shared__ float sJ[2][WW + 2 * PAD];

    const int t = threadIdx.x;
    const int plane = blockIdx.x;              // n*DD + d
    const int h0 = blockIdx.y * CH;
    const float* Ip = I + (size_t)plane * HW;
    const float* Jp = J + (size_t)plane * HW;
    const size_t obase = (size_t)plane * HW;

    const int wld = t - PAD;                   // column this thread loads (halo)
    const bool lane_ok = (t < WW + 2 * PAD);
    const bool ld_ok = lane_ok && ((unsigned)wld < (unsigned)WW);

    float r0[9], r1[9], r2[9], r3[9], r4[9];
#pragma unroll
    for (int k = 0; k < 9; k++) { r0[k] = r1[k] = r2[k] = r3[k] = r4[k] = 0.f; }
    float S0 = 0.f, S1 = 0.f, S2 = 0.f, S3 = 0.f, S4 = 0.f;

    // Prefetch step 0 (row h0 - PAD)
    float vi = 0.f, vj = 0.f;
    {
        const int hh = h0 - PAD;
        if (ld_ok && (unsigned)hh < (unsigned)HH) {
            const size_t p = (size_t)hh * WW + wld;
            vi = Ip[p]; vj = Jp[p];
        }
    }

    for (int hb = 0; hb < NSTEPS; hb += 18) {
#pragma unroll
        for (int k = 0; k < 18; k++) {
            const int step = hb + k;
            const int buf = k & 1;             // 18 even -> continuous across hb
            const int rs = k % 9;              // == step % 9 (hb multiple of 9)

            // publish prefetched row
            if (lane_ok) {
                sI[buf][t] = vi;
                sJ[buf][t] = vj;
            }

            // prefetch next row (independent of smem/compute)
            {
                const int hh = h0 - PAD + step + 1;
                vi = 0.f; vj = 0.f;
                if (ld_ok && (unsigned)hh < (unsigned)HH) {
                    const size_t p = (size_t)hh * WW + wld;
                    vi = Ip[p]; vj = Jp[p];
                }
            }

            __syncthreads();

            if (t < WW) {
                float v0 = 0.f, v1 = 0.f, v2 = 0.f, v3 = 0.f, v4 = 0.f;
#pragma unroll
                for (int q = 0; q < 9; q++) {
                    const float a = sI[buf][t + q];
                    const float b = sJ[buf][t + q];
                    v0 += a; v1 += b;
                    v2 += a * a; v3 += b * b; v4 += a * b;
                }
                // H sliding window via register ring
                S0 += v0 - r0[rs]; r0[rs] = v0;
                S1 += v1 - r1[rs]; r1[rs] = v1;
                S2 += v2 - r2[rs]; r2[rs] = v2;
                S3 += v3 - r3[rs]; r3[rs] = v3;
                S4 += v4 - r4[rs]; r4[rs] = v4;

                if (step >= 2 * PAD) {
                    const int ho = h0 + step - 2 * PAD;
                    const size_t idx = obase + (size_t)ho * WW + t;
                    g_B4[idx] = make_float4(S0, S1, S2, S3);
                    g_B1[idx] = S4;
                }
            }
            // no second sync: next step's barrier separates buf reuse
        }
    }
}

// ---------------------------------------------------------------------------
// k3: D-axis sliding box sum fused with NCC pointwise loss + block reduction.
// Thread = (n, d-chunk, h, w). Coalesced along w; float4 + float loads.
// ---------------------------------------------------------------------------
__global__ __launch_bounds__(256) void k3_dpass() {
    const int t = blockIdx.x * blockDim.x + threadIdx.x;
    float local = 0.f;

    if (t < T3) {
        int w = t % WW;
        int r = t / WW;
        int h = r % HH; r /= HH;
        int chunk = r & (NCD - 1);
        int n = r >> 1;
        int d0 = chunk * CHD;
        size_t base = (size_t)n * DHW + (size_t)h * WW + w;

        float S0 = 0.f, S1 = 0.f, S2 = 0.f, S3 = 0.f, S4 = 0.f;
#pragma unroll
        for (int k = -PAD; k <= PAD; k++) {
            int dd = d0 + k;
            if ((unsigned)dd < (unsigned)DD) {
                size_t p = base + (size_t)dd * HW;
                float4 f = g_B4[p];
                S0 += f.x; S1 += f.y; S2 += f.z; S3 += f.w;
                S4 += g_B1[p];
            }
        }

        const float ws = 729.f, inv_ws = 1.f / 729.f;

#pragma unroll 4
        for (int d = d0; d < d0 + CHD; d++) {
            float ui = S0 * inv_ws;
            float uj = S1 * inv_ws;
            float cross = S4 - uj * S0 - ui * S1 + ui * uj * ws;
            float iv = fmaxf(S2 - 2.f * ui * S0 + ui * ui * ws, EPSV);
            float jv = fmaxf(S3 - 2.f * uj * S1 + uj * uj * ws, EPSV);
            local += (cross * cross) / (iv * jv);

            int da = d + PAD + 1;
            int ds = d - PAD;
            if ((unsigned)da < (unsigned)DD) {
                size_t q = base + (size_t)da * HW;
                float4 f = g_B4[q];
                S0 += f.x; S1 += f.y; S2 += f.z; S3 += f.w;
                S4 += g_B1[q];
            }
            if ((unsigned)ds < (unsigned)DD) {
                size_t q = base + (size_t)ds * HW;
                float4 f = g_B4[q];
                S0 -= f.x; S1 -= f.y; S2 -= f.z; S3 -= f.w;
                S4 -= g_B1[q];
            }
        }
    }

#pragma unroll
    for (int o = 16; o > 0; o >>= 1)
        local += __shfl_down_sync(0xffffffffu, local, o);

    __shared__ float wsum[8];
    if ((threadIdx.x & 31) == 0) wsum[threadIdx.x >> 5] = local;
    __syncthreads();
    if (threadIdx.x == 0) {
        float s = 0.f;
#pragma unroll
        for (int i = 0; i < 8; i++) s += wsum[i];
        g_part[blockIdx.x] = (double)s;
    }
}

// ---------------------------------------------------------------------------
// Final: parallel deterministic reduction of 672 partials.
// ---------------------------------------------------------------------------
__global__ __launch_bounds__(256) void k_final(float* __restrict__ out) {
    __shared__ double sd[256];
    const int t = threadIdx.x;
    double s = 0.0;
    for (int i = t; i < K3_BLOCKS; i += 256) s += g_part[i];
    sd[t] = s;
    __syncthreads();
#pragma unroll
    for (int o = 128; o > 0; o >>= 1) {
        if (t < o) sd[t] += sd[t + o];
        __syncthreads();
    }
    if (t == 0) out[0] = (float)(-sd[0] / (double)VOLI);
}

extern "C" void kernel_launch(void* const* d_in, const int* in_sizes, int n_in,
                              void* d_out, int out_size) {
    const float* I = (const float*)d_in[0];   // y_true
    const float* J = (const float*)d_in[1];   // y_pred

    dim3 gridA(NB * DD, HH / CH);             // (320, 3)
    kA<<<gridA, 256>>>(I, J);
    k3_dpass<<<K3_BLOCKS, 256>>>();
    k_final<<<1, 256>>>((float*)d_out);
}

// round 7
// speedup vs baseline: 2.4170x; 1.2739x over previous
#include <cuda_runtime.h>

// Geometry: (N=2, C=1, D=160, H=192, W=224), win=9, pad=4, zero-padded box sums.
#define NB   2
#define DD   160
#define HH   192
#define WW   224
#define HW   (HH * WW)            // 43008
#define DHW  (DD * HW)            // 6881280
#define VOLI (NB * DHW)           // 13762560
#define PAD  4
#define EPSV 1e-5f
#define SZ   ((size_t)VOLI)

#define CH     64                 // h-chunk per block in kA
#define NSTEPS (CH + 2 * PAD)     // 72
#define ROWL   (WW + 2 * PAD)     // 232

#define CHD  80                   // d-chunk per thread in k3
#define NCD  2
#define T3   (NB * NCD * HH * WW) // 172032
#define K3_BLOCKS (T3 / 256)      // 672

// Scratch: W+H box-summed fields. float4 = (sumI,sumJ,sumI2,sumJ2), float = sumIJ.
__device__ float4 g_B4[SZ];
__device__ float  g_B1[SZ];
__device__ double g_part[K3_BLOCKS];

// ---------------------------------------------------------------------------
// kA: fused W-pass + H-pass, software-pipelined, H-ring in SHARED MEMORY.
// Block = (plane, h-chunk of 64). Thread t owns column w=t.
// Per step: publish prefetched row to smem (double buffered), prefetch next
// row, one __syncthreads, compute 9-tap W sums, slide the H window using a
// 9-deep per-column ring that lives in smem (column-private -> no extra sync,
// no register pressure). Regs drop ~74 -> ~40 so occupancy is smem-limited
// at 4 blocks/SM (50%) instead of register-limited at 3 (37.5%).
// ---------------------------------------------------------------------------
__global__ __launch_bounds__(256) void kA(const float* __restrict__ I,
                                          const float* __restrict__ J) {
    __shared__ float4 ringQ[9][ROWL];   // 33,408 B : (v0,v1,v2,v3) history
    __shared__ float  ringS[9][ROWL];   //  8,352 B : v4 history
    __shared__ float  sI[2][ROWL];      //  1,856 B
    __shared__ float  sJ[2][ROWL];      //  1,856 B

    const int t = threadIdx.x;
    const int plane = blockIdx.x;              // n*DD + d
    const int h0 = blockIdx.y * CH;
    const float* Ip = I + (size_t)plane * HW;
    const float* Jp = J + (size_t)plane * HW;
    const size_t obase = (size_t)plane * HW;

    const int wld = t - PAD;                   // column this thread loads (halo)
    const bool lane_ok = (t < ROWL);
    const bool ld_ok = lane_ok && ((unsigned)wld < (unsigned)WW);

    // Zero-init ring (column-private; visibility guaranteed by step-0 barrier).
    if (t < ROWL) {
#pragma unroll
        for (int s = 0; s < 9; s++) {
            ringQ[s][t] = make_float4(0.f, 0.f, 0.f, 0.f);
            ringS[s][t] = 0.f;
        }
    }

    float S0 = 0.f, S1 = 0.f, S2 = 0.f, S3 = 0.f, S4 = 0.f;

    // Prefetch step 0 (row h0 - PAD)
    float vi = 0.f, vj = 0.f;
    {
        const int hh = h0 - PAD;
        if (ld_ok && (unsigned)hh < (unsigned)HH) {
            const size_t p = (size_t)hh * WW + wld;
            vi = Ip[p]; vj = Jp[p];
        }
    }

    int rs = 0;                                // ring slot = step % 9
#pragma unroll 2
    for (int step = 0; step < NSTEPS; step++) {
        const int buf = step & 1;

        // publish prefetched row
        if (lane_ok) {
            sI[buf][t] = vi;
            sJ[buf][t] = vj;
        }

        // prefetch next row (independent of smem/compute)
        {
            const int hh = h0 - PAD + step + 1;
            vi = 0.f; vj = 0.f;
            if (ld_ok && (unsigned)hh < (unsigned)HH) {
                const size_t p = (size_t)hh * WW + wld;
                vi = Ip[p]; vj = Jp[p];
            }
        }

        __syncthreads();

        if (t < WW) {
            float v0 = 0.f, v1 = 0.f, v2 = 0.f, v3 = 0.f, v4 = 0.f;
#pragma unroll
            for (int q = 0; q < 9; q++) {
                const float a = sI[buf][t + q];
                const float b = sJ[buf][t + q];
                v0 += a; v1 += b;
                v2 += a * a; v3 += b * b; v4 += a * b;
            }
            // H sliding window via smem ring (own column only)
            const float4 o4 = ringQ[rs][t];
            const float  o1 = ringS[rs][t];
            S0 += v0 - o4.x;
            S1 += v1 - o4.y;
            S2 += v2 - o4.z;
            S3 += v3 - o4.w;
            S4 += v4 - o1;
            ringQ[rs][t] = make_float4(v0, v1, v2, v3);
            ringS[rs][t] = v4;

            if (step >= 2 * PAD) {
                const int ho = h0 + step - 2 * PAD;
                const size_t idx = obase + (size_t)ho * WW + t;
                g_B4[idx] = make_float4(S0, S1, S2, S3);
                g_B1[idx] = S4;
            }
        }
        rs = (rs == 8) ? 0 : rs + 1;
        // no second sync: next step's barrier separates row-buffer reuse
    }
}

// ---------------------------------------------------------------------------
// k3: D-axis sliding box sum fused with NCC pointwise loss + block reduction.
// Thread = (n, d-chunk, h, w). Coalesced along w; float4 + float loads.
// ---------------------------------------------------------------------------
__global__ __launch_bounds__(256) void k3_dpass() {
    const int t = blockIdx.x * blockDim.x + threadIdx.x;
    float local = 0.f;

    if (t < T3) {
        int w = t % WW;
        int r = t / WW;
        int h = r % HH; r /= HH;
        int chunk = r & (NCD - 1);
        int n = r >> 1;
        int d0 = chunk * CHD;
        size_t base = (size_t)n * DHW + (size_t)h * WW + w;

        float S0 = 0.f, S1 = 0.f, S2 = 0.f, S3 = 0.f, S4 = 0.f;
#pragma unroll
        for (int k = -PAD; k <= PAD; k++) {
            int dd = d0 + k;
            if ((unsigned)dd < (unsigned)DD) {
                size_t p = base + (size_t)dd * HW;
                float4 f = g_B4[p];
                S0 += f.x; S1 += f.y; S2 += f.z; S3 += f.w;
                S4 += g_B1[p];
            }
        }

        const float ws = 729.f, inv_ws = 1.f / 729.f;

#pragma unroll 4
        for (int d = d0; d < d0 + CHD; d++) {
            float ui = S0 * inv_ws;
            float uj = S1 * inv_ws;
            float cross = S4 - uj * S0 - ui * S1 + ui * uj * ws;
            float iv = fmaxf(S2 - 2.f * ui * S0 + ui * ui * ws, EPSV);
            float jv = fmaxf(S3 - 2.f * uj * S1 + uj * uj * ws, EPSV);
            local += (cross * cross) / (iv * jv);

            int da = d + PAD + 1;
            int ds = d - PAD;
            if ((unsigned)da < (unsigned)DD) {
                size_t q = base + (size_t)da * HW;
                float4 f = g_B4[q];
                S0 += f.x; S1 += f.y; S2 += f.z; S3 += f.w;
                S4 += g_B1[q];
            }
            if ((unsigned)ds < (unsigned)DD) {
                size_t q = base + (size_t)ds * HW;
                float4 f = g_B4[q];
                S0 -= f.x; S1 -= f.y; S2 -= f.z; S3 -= f.w;
                S4 -= g_B1[q];
            }
        }
    }

#pragma unroll
    for (int o = 16; o > 0; o >>= 1)
        local += __shfl_down_sync(0xffffffffu, local, o);

    __shared__ float wsum[8];
    if ((threadIdx.x & 31) == 0) wsum[threadIdx.x >> 5] = local;
    __syncthreads();
    if (threadIdx.x == 0) {
        float s = 0.f;
#pragma unroll
        for (int i = 0; i < 8; i++) s += wsum[i];
        g_part[blockIdx.x] = (double)s;
    }
}

// ---------------------------------------------------------------------------
// Final: parallel deterministic reduction of 672 partials.
// ---------------------------------------------------------------------------
__global__ __launch_bounds__(256) void k_final(float* __restrict__ out) {
    __shared__ double sd[256];
    const int t = threadIdx.x;
    double s = 0.0;
    for (int i = t; i < K3_BLOCKS; i += 256) s += g_part[i];
    sd[t] = s;
    __syncthreads();
#pragma unroll
    for (int o = 128; o > 0; o >>= 1) {
        if (t < o) sd[t] += sd[t + o];
        __syncthreads();
    }
    if (t == 0) out[0] = (float)(-sd[0] / (double)VOLI);
}

extern "C" void kernel_launch(void* const* d_in, const int* in_sizes, int n_in,
                              void* d_out, int out_size) {
    const float* I = (const float*)d_in[0];   // y_true
    const float* J = (const float*)d_in[1];   // y_pred

    dim3 gridA(NB * DD, HH / CH);             // (320, 3)
    kA<<<gridA, 256>>>(I, J);
    k3_dpass<<<K3_BLOCKS, 256>>>();
    k_final<<<1, 256>>>((float*)d_out);
}